// round 14
// baseline (speedup 1.0000x reference)
#include <cuda_runtime.h>
#include <cuda_bf16.h>
#include <math.h>
#include <stdint.h>

// ---------------------------------------------------------------------------
// Problem constants
// ---------------------------------------------------------------------------
#define S_LEN 2048
#define H_DIM 2048
#define NH 32
#define QLR 1344
#define QLR_PAD 1408
#define KVLR 128
#define DN 32
#define DR 32
#define DV 64
#define HD 64
#define KV_COLS 160
#define KV_PAD 256
#define KVU_COLS 3072
#define Q_COLS 2048
#define CTX_COLS 2048

// ---------------------------------------------------------------------------
// Scratch (device globals — no allocation allowed)
// ---------------------------------------------------------------------------
__device__ float g_qc [S_LEN * QLR];
__device__ float g_q  [S_LEN * Q_COLS];
__device__ float g_kv [S_LEN * KV_COLS];
__device__ float g_kvu[S_LEN * KVU_COLS];
__device__ float g_cos[S_LEN * 16];
__device__ float g_sin[S_LEN * 16];

// split activations (bf16 hi/lo)
__device__ __nv_bfloat16 g_xh [S_LEN * H_DIM],  g_xl [S_LEN * H_DIM];
__device__ __nv_bfloat16 g_qch[S_LEN * QLR],    g_qcl[S_LEN * QLR];
__device__ __nv_bfloat16 g_kch[S_LEN * KVLR],   g_kcl[S_LEN * KVLR];
__device__ __nv_bfloat16 g_cxh[S_LEN * CTX_COLS], g_cxl[S_LEN * CTX_COLS];
// split + transposed weights: [Npad, K]
__device__ __nv_bfloat16 g_wqdh[QLR_PAD * H_DIM], g_wqdl[QLR_PAD * H_DIM];
__device__ __nv_bfloat16 g_wquh[Q_COLS * QLR],    g_wqul[Q_COLS * QLR];
__device__ __nv_bfloat16 g_wkdh[KV_PAD * H_DIM],  g_wkdl[KV_PAD * H_DIM];
__device__ __nv_bfloat16 g_wkuh[KVU_COLS * KVLR], g_wkul[KVU_COLS * KVLR];
__device__ __nv_bfloat16 g_woh [H_DIM * CTX_COLS], g_wol[H_DIM * CTX_COLS];
// attention operands (bf16 hi/lo, pre-split)
__device__ __nv_bfloat16 g_qsh[S_LEN * Q_COLS],  g_qsl[S_LEN * Q_COLS];   // scaled+roped Q
__device__ __nv_bfloat16 g_akh[NH * S_LEN * HD], g_akl[NH * S_LEN * HD];  // K per head [h][t][64]
__device__ __nv_bfloat16 g_avh[NH * DV * S_LEN], g_avl[NH * DV * S_LEN];  // V^T per head [h][d][t]

// ---------------------------------------------------------------------------
// PTX helpers
// ---------------------------------------------------------------------------
__device__ __forceinline__ uint32_t smem_u32(const void* p) {
    uint32_t a;
    asm("{ .reg .u64 t; cvta.to.shared.u64 t, %1; cvt.u32.u64 %0, t; }" : "=r"(a) : "l"(p));
    return a;
}
__device__ __forceinline__ void mma16816(float* d, const uint32_t* a, const uint32_t* b)
{
    asm volatile(
        "mma.sync.aligned.m16n8k16.row.col.f32.bf16.bf16.f32 "
        "{%0,%1,%2,%3}, {%4,%5,%6,%7}, {%8,%9}, {%0,%1,%2,%3};"
        : "+f"(d[0]), "+f"(d[1]), "+f"(d[2]), "+f"(d[3])
        : "r"(a[0]), "r"(a[1]), "r"(a[2]), "r"(a[3]),
          "r"(b[0]), "r"(b[1]));
}
__device__ __forceinline__ void ldm4(uint32_t* r, uint32_t addr)
{
    asm volatile("ldmatrix.sync.aligned.m8n8.x4.shared.b16 {%0,%1,%2,%3}, [%4];"
        : "=r"(r[0]), "=r"(r[1]), "=r"(r[2]), "=r"(r[3]) : "r"(addr));
}
__device__ __forceinline__ void cp16cg(uint32_t saddr, const void* gaddr)
{
    asm volatile("cp.async.cg.shared.global [%0], [%1], 16;" :: "r"(saddr), "l"(gaddr));
}
__device__ __forceinline__ void cp_commit() { asm volatile("cp.async.commit_group;"); }
template <int N> __device__ __forceinline__ void cp_wait()
{
    asm volatile("cp.async.wait_group %0;" :: "n"(N));
}
// 64B-row swizzle (4 x 16B chunks) — GEMM tiles
__device__ __forceinline__ uint32_t swz(int row, int c)
{
    return (uint32_t)(row * 64 + ((c ^ ((row >> 1) & 3)) << 4));
}
// 128B-row swizzle (8 x 16B chunks) — attention tiles
__device__ __forceinline__ uint32_t swz8(int row, int c)
{
    return (uint32_t)(row * 128 + ((c ^ (row & 7)) << 4));
}
__device__ __forceinline__ uint32_t pack_bf2(float a, float b)
{
    __nv_bfloat162 t = __floats2bfloat162_rn(a, b);
    return *(uint32_t*)&t;
}

// ---------------------------------------------------------------------------
// GEMM (R12 config, best measured): C[M,N] fp32 = A[M,K] @ B^T, bf16 hi/lo.
// CTA 128x64x32, 8 warps (4M x 2N), warp tile 32x32. 2-stage, 48KB smem,
// launch_bounds(256,2) -> 2 CTAs/SM.
// ---------------------------------------------------------------------------
#define ST_AH 0
#define ST_AL 8192
#define ST_BH 16384
#define ST_BL 20480
#define ST_SZ 24576

__global__ __launch_bounds__(256, 2) void mma_gemm2(
    const __nv_bfloat16* __restrict__ Ah, const __nv_bfloat16* __restrict__ Al,
    const __nv_bfloat16* __restrict__ Bh, const __nv_bfloat16* __restrict__ Bl,
    float* __restrict__ C, int M, int N, int K)
{
    extern __shared__ uint8_t dsm[];
    const uint32_t sbase = smem_u32(dsm);
    const int tid = threadIdx.x, lane = tid & 31, wid = tid >> 5;
    const int wm = wid & 3, wn = wid >> 2;
    const int m0 = blockIdx.y * 128, n0 = blockIdx.x * 64;
    const int g = lane >> 2, t2 = (lane & 3) * 2;

    float acc[2][4][4];
#pragma unroll
    for (int mi = 0; mi < 2; mi++)
#pragma unroll
        for (int ni = 0; ni < 4; ni++)
#pragma unroll
            for (int j = 0; j < 4; j++) acc[mi][ni][j] = 0.f;

    auto load_stage = [&](int s, int k0) {
        uint32_t sb = sbase + s * ST_SZ;
#pragma unroll
        for (int i = 0; i < 4; i++) {
            int u = tid + 256 * i;
            int v = u & 511;
            int row = v >> 2, c = v & 3;
            uint32_t soff = swz(row, c);
            const __nv_bfloat16* gp = (i < 2) ? Ah : Al;
            uint32_t so = (i < 2) ? ST_AH : ST_AL;
            cp16cg(sb + so + soff, gp + (size_t)(m0 + row) * K + k0 + c * 8);
        }
        {
            int v = tid & 255;
            int row = v >> 2, c = v & 3;
            uint32_t soff = swz(row, c);
            cp16cg(sb + ST_BH + soff, Bh + (size_t)(n0 + row) * K + k0 + c * 8);
            cp16cg(sb + ST_BL + soff, Bl + (size_t)(n0 + row) * K + k0 + c * 8);
        }
    };

    const int nch = K / 32;
    load_stage(0, 0);
    cp_commit();

    for (int ci = 0; ci < nch; ci++) {
        if (ci + 1 < nch) {
            load_stage((ci + 1) & 1, (ci + 1) * 32);
            cp_commit();
            cp_wait<1>();
        } else {
            cp_wait<0>();
        }
        __syncthreads();

        const uint32_t sa = sbase + (ci & 1) * ST_SZ;
#pragma unroll
        for (int ks = 0; ks < 2; ks++) {
            uint32_t ah[2][4], alr[2][4];
#pragma unroll
            for (int mi = 0; mi < 2; mi++) {
                int row = wm * 32 + mi * 16 + (lane & 15);
                int c = 2 * ks + (lane >> 4);
                uint32_t off = swz(row, c);
                ldm4(ah[mi],  sa + ST_AH + off);
                ldm4(alr[mi], sa + ST_AL + off);
            }
            uint32_t bh[4][2], bl[4][2];
#pragma unroll
            for (int p = 0; p < 2; p++) {
                int row = wn * 32 + p * 16 + ((lane >> 4) & 1) * 8 + (lane & 7);
                int c = 2 * ks + ((lane >> 3) & 1);
                uint32_t off = swz(row, c);
                uint32_t th[4], tl[4];
                ldm4(th, sa + ST_BH + off);
                ldm4(tl, sa + ST_BL + off);
                bh[2*p][0] = th[0]; bh[2*p][1] = th[1];
                bh[2*p+1][0] = th[2]; bh[2*p+1][1] = th[3];
                bl[2*p][0] = tl[0]; bl[2*p][1] = tl[1];
                bl[2*p+1][0] = tl[2]; bl[2*p+1][1] = tl[3];
            }
#pragma unroll
            for (int mi = 0; mi < 2; mi++)
#pragma unroll
                for (int ni = 0; ni < 4; ni++) {
                    mma16816(acc[mi][ni], ah[mi],  bh[ni]);
                    mma16816(acc[mi][ni], ah[mi],  bl[ni]);
                    mma16816(acc[mi][ni], alr[mi], bh[ni]);
                }
        }
        __syncthreads();
    }

#pragma unroll
    for (int mi = 0; mi < 2; mi++) {
        int row = m0 + wm * 32 + mi * 16 + g;
#pragma unroll
        for (int ni = 0; ni < 4; ni++) {
            int col = n0 + wn * 32 + ni * 8 + t2;
            if (col < N) {
                float2 v0 = {acc[mi][ni][0], acc[mi][ni][1]};
                float2 v1 = {acc[mi][ni][2], acc[mi][ni][3]};
                *(float2*)&C[(size_t)row * N + col]       = v0;
                *(float2*)&C[(size_t)(row + 8) * N + col] = v1;
            }
        }
    }
}

// ---------------------------------------------------------------------------
// Weight transpose + split
// ---------------------------------------------------------------------------
__global__ void wsplit_t(const float* __restrict__ W,
                         __nv_bfloat16* __restrict__ Th,
                         __nv_bfloat16* __restrict__ Tl,
                         int Kw, int Nw)
{
    __shared__ float t[32][33];
    int n0 = blockIdx.x * 32, k0 = blockIdx.y * 32;
    int tx = threadIdx.x, ty = threadIdx.y;
#pragma unroll
    for (int j = 0; j < 32; j += 8) {
        int k = k0 + ty + j, n = n0 + tx;
        t[ty + j][tx] = (n < Nw) ? W[(size_t)k * Nw + n] : 0.f;
    }
    __syncthreads();
#pragma unroll
    for (int j = 0; j < 32; j += 8) {
        int n = n0 + ty + j, k = k0 + tx;
        float v = t[tx][ty + j];
        __nv_bfloat16 h = __float2bfloat16(v);
        Th[(size_t)n * Kw + k] = h;
        Tl[(size_t)n * Kw + k] = __float2bfloat16(v - __bfloat162float(h));
    }
}

// ---------------------------------------------------------------------------
// fp32 -> bf16 hi/lo split (vectorized)
// ---------------------------------------------------------------------------
__global__ void split_kernel(const float* __restrict__ x,
                             __nv_bfloat16* __restrict__ h,
                             __nv_bfloat16* __restrict__ l, int n4)
{
    int i = blockIdx.x * blockDim.x + threadIdx.x;
    if (i >= n4) return;
    float4 v = ((const float4*)x)[i];
    float vv[4] = {v.x, v.y, v.z, v.w};
    __nv_bfloat16 hh[4], ll[4];
#pragma unroll
    for (int k = 0; k < 4; k++) {
        hh[k] = __float2bfloat16(vv[k]);
        ll[k] = __float2bfloat16(vv[k] - __bfloat162float(hh[k]));
    }
    ((uint2*)h)[i] = *(uint2*)hh;
    ((uint2*)l)[i] = *(uint2*)ll;
}

// ---------------------------------------------------------------------------
// RMSNorm with fused bf16 hi/lo split output
// ---------------------------------------------------------------------------
__global__ void rmsnorm_split(const float* __restrict__ in,
                              __nv_bfloat16* __restrict__ oh,
                              __nv_bfloat16* __restrict__ ol,
                              const float* __restrict__ w, const float* __restrict__ b,
                              int cols, int in_ld)
{
    int row = blockIdx.x;
    const float* x = in + (size_t)row * in_ld;
    float ss = 0.f;
    for (int c = threadIdx.x; c < cols; c += blockDim.x) {
        float v = x[c];
        ss = fmaf(v, v, ss);
    }
    __shared__ float red[8];
#pragma unroll
    for (int o = 16; o > 0; o >>= 1) ss += __shfl_down_sync(0xffffffffu, ss, o);
    if ((threadIdx.x & 31) == 0) red[threadIdx.x >> 5] = ss;
    __syncthreads();
    if (threadIdx.x == 0) {
        float tot = 0.f;
        for (int i = 0; i < (int)(blockDim.x >> 5); i++) tot += red[i];
        red[0] = rsqrtf(tot / (float)cols + 1e-5f);
    }
    __syncthreads();
    float inv = red[0];
    for (int c = threadIdx.x; c < cols; c += blockDim.x) {
        float v = fmaf(w[c], x[c] * inv, b[c]);
        __nv_bfloat16 h = __float2bfloat16(v);
        oh[(size_t)row * cols + c] = h;
        ol[(size_t)row * cols + c] = __float2bfloat16(v - __bfloat162float(h));
    }
}

// ---------------------------------------------------------------------------
// RoPE table
// ---------------------------------------------------------------------------
__global__ void rope_table_kernel()
{
    int idx = blockIdx.x * blockDim.x + threadIdx.x;
    if (idx >= S_LEN * 16) return;
    int t = idx >> 4, i = idx & 15;
    double inv_freq = exp(-((double)(2 * i) / 32.0) * log(500000.0));
    double a = (double)t * inv_freq;
    g_cos[idx] = (float)cos(a);
    g_sin[idx] = (float)sin(a);
}

// ---------------------------------------------------------------------------
// Fused: rope(q) + scale + bf16 split
// ---------------------------------------------------------------------------
__global__ void rope_q_split_kernel()
{
    int idx = blockIdx.x * blockDim.x + threadIdx.x;
    if (idx >= S_LEN * NH) return;
    int s = idx / NH, h = idx % NH;
    const float* p = g_q + (size_t)s * Q_COLS + h * HD;
    float v[64];
#pragma unroll
    for (int d = 0; d < 64; d += 4) {
        float4 t = *(const float4*)&p[d];
        v[d] = t.x; v[d+1] = t.y; v[d+2] = t.z; v[d+3] = t.w;
    }
    float x[32];
#pragma unroll
    for (int i = 0; i < 32; i++) x[i] = v[32 + i];
#pragma unroll
    for (int i = 0; i < 16; i++) {
        float c = g_cos[s * 16 + i], sn = g_sin[s * 16 + i];
        v[32 + i] = fmaf(x[2 * i], c, -x[2 * i + 1] * sn);
        v[48 + i] = fmaf(x[2 * i + 1], c, x[2 * i] * sn);
    }
    size_t base = (size_t)s * Q_COLS + h * HD;
#pragma unroll
    for (int d = 0; d < 64; d += 2) {
        float a = v[d] * 0.125f, b = v[d + 1] * 0.125f;
        __nv_bfloat162 hh = __floats2bfloat162_rn(a, b);
        *(uint32_t*)&g_qsh[base + d] = *(uint32_t*)&hh;
        *(uint32_t*)&g_qsl[base + d] =
            pack_bf2(a - __bfloat162float(hh.x), b - __bfloat162float(hh.y));
    }
}

__global__ void rope_k_kernel()
{
    int s = blockIdx.x * blockDim.x + threadIdx.x;
    if (s >= S_LEN) return;
    float* p = g_kv + (size_t)s * KV_COLS + KVLR;
    float x[32];
#pragma unroll
    for (int i = 0; i < 32; i++) x[i] = p[i];
#pragma unroll
    for (int i = 0; i < 16; i++) {
        float c = g_cos[s * 16 + i], sn = g_sin[s * 16 + i];
        p[i]      = fmaf(x[2 * i], c, -x[2 * i + 1] * sn);
        p[i + 16] = fmaf(x[2 * i + 1], c, x[2 * i] * sn);
    }
}

// ---------------------------------------------------------------------------
// Attention pre-pass: assemble K per head (bf16 hi/lo) [h][t][64]
// ---------------------------------------------------------------------------
__global__ void ksplit_kernel()
{
    int u = blockIdx.x * blockDim.x + threadIdx.x;
    if (u >= NH * S_LEN * HD) return;
    int d = u & 63, t = (u >> 6) & 2047, h = u >> 17;
    float v = (d < DN) ? g_kvu[(size_t)t * KVU_COLS + h * 96 + d]
                       : g_kv [(size_t)t * KV_COLS + KVLR + (d - DN)];
    __nv_bfloat16 hh = __float2bfloat16(v);
    g_akh[u] = hh;
    g_akl[u] = __float2bfloat16(v - __bfloat162float(hh));
}

// ---------------------------------------------------------------------------
// Attention pre-pass: transpose V per head -> [h][d][t], bf16 hi/lo
// ---------------------------------------------------------------------------
__global__ void vtsplit_kernel()
{
    __shared__ float sm[32][33];
    int t0 = blockIdx.x * 32, d0 = blockIdx.y * 32, h = blockIdx.z;
    int tx = threadIdx.x, ty = threadIdx.y;
#pragma unroll
    for (int j = 0; j < 32; j += 8) {
        int t = t0 + ty + j, d = d0 + tx;
        sm[ty + j][tx] = g_kvu[(size_t)t * KVU_COLS + h * 96 + DN + d];
    }
    __syncthreads();
#pragma unroll
    for (int j = 0; j < 32; j += 8) {
        int d = d0 + ty + j, t = t0 + tx;
        float v = sm[tx][ty + j];
        __nv_bfloat16 hh = __float2bfloat16(v);
        size_t idx = ((size_t)h * DV + d) * S_LEN + t;
        g_avh[idx] = hh;
        g_avl[idx] = __float2bfloat16(v - __bfloat162float(hh));
    }
}

// ---------------------------------------------------------------------------
// Tensor-core flash attention (causal), double-buffered K/V staging.
// smem 64KB: KV buf0 at 0, KV buf1 at 32K. Q staged into buf1's region
// (fragments are register-resident before buf1 is first overwritten by the
// kt=1 prefetch; __syncthreads() after the fragment loads guards the reuse).
// launch_bounds(256,2): 2 CTAs/SM (2x64KB smem, regs clamped to 128).
// ---------------------------------------------------------------------------
__global__ __launch_bounds__(256, 2) void attn_mma_kernel()
{
    extern __shared__ uint8_t dsm[];
    const int qb = 15 - blockIdx.x;        // heavy blocks first
    const int h  = blockIdx.y;
    const int tid = threadIdx.x, lane = tid & 31, w = tid >> 5;
    const int g = lane >> 2, t2 = (lane & 3) * 2;
    const uint32_t sb = smem_u32(dsm);

    auto stage_kv = [&](int buf, int kt) {
        uint32_t skv = sb + buf * 32768;
#pragma unroll
        for (int i = 0; i < 8; i++) {
            int u = tid + 256 * i;
            int arr = u >> 9;
            int v = u & 511;
            int row = v >> 3, c = v & 7;
            const __nv_bfloat16* src;
            if (arr == 0)
                src = g_akh + ((size_t)h * S_LEN + kt * 64 + row) * HD + c * 8;
            else if (arr == 1)
                src = g_akl + ((size_t)h * S_LEN + kt * 64 + row) * HD + c * 8;
            else if (arr == 2)
                src = g_avh + ((size_t)h * DV + row) * S_LEN + kt * 64 + c * 8;
            else
                src = g_avl + ((size_t)h * DV + row) * S_LEN + kt * 64 + c * 8;
            cp16cg(skv + arr * 8192 + swz8(row, c), src);
        }
    };

    // stage Q (hi/lo) into buf1's region + first KV tile into buf0
#pragma unroll
    for (int i = 0; i < 8; i++) {
        int u = tid + 256 * i;
        int half = u >> 10;
        int v = u & 1023;
        int row = v >> 3, c = v & 7;
        const __nv_bfloat16* src = (half ? g_qsl : g_qsh)
            + (size_t)(qb * 128 + row) * Q_COLS + h * HD + c * 8;
        cp16cg(sb + 32768 + half * 16384 + swz8(row, c), src);
    }
    cp_commit();
    stage_kv(0, 0);
    cp_commit();
    cp_wait<0>();
    __syncthreads();

    uint32_t qh[4][4], ql[4][4];
    {
        int row = w * 16 + (lane & 15);
#pragma unroll
        for (int ks = 0; ks < 4; ks++) {
            int c = 2 * ks + (lane >> 4);
            uint32_t off = swz8(row, c);
            ldm4(qh[ks], sb + 32768 + off);
            ldm4(ql[ks], sb + 49152 + off);
        }
    }
    __syncthreads();   // all Q fragments loaded before buf1 is overwritten

    float o[8][4];
#pragma unroll
    for (int nd = 0; nd < 8; nd++)
#pragma unroll
        for (int j = 0; j < 4; j++) o[nd][j] = 0.f;
    float m0 = -INFINITY, m1 = -INFINITY, l0 = 0.f, l1 = 0.f;

    const int row0 = qb * 128 + w * 16 + g;
    const int row1 = row0 + 8;
    const int wmax = qb * 128 + w * 16 + 15;
    const int ktmax = 2 * qb + 1;

    for (int kt = 0; kt <= ktmax; kt++) {
        if (kt + 1 <= ktmax) {
            stage_kv((kt + 1) & 1, kt + 1);
            cp_commit();
            cp_wait<1>();
        } else {
            cp_wait<0>();
        }
        __syncthreads();

        const uint32_t skv = sb + (kt & 1) * 32768;

        if (kt * 64 <= wmax) {
            float s[8][4];
#pragma unroll
            for (int ni = 0; ni < 8; ni++)
#pragma unroll
                for (int j = 0; j < 4; j++) s[ni][j] = 0.f;

            {
                int krow = ((lane >> 4) & 1) * 8 + (lane & 7);
                int ksel = (lane >> 3) & 1;
#pragma unroll
                for (int ks = 0; ks < 4; ks++) {
                    uint32_t kh[4][4], kl[4][4];
                    int c = 2 * ks + ksel;
#pragma unroll
                    for (int p = 0; p < 4; p++) {
                        uint32_t off = swz8(p * 16 + krow, c);
                        ldm4(kh[p], skv + off);
                        ldm4(kl[p], skv + 8192 + off);
                    }
#pragma unroll
                    for (int ni = 0; ni < 8; ni++) {
                        const uint32_t* bh = &kh[ni >> 1][(ni & 1) * 2];
                        const uint32_t* bl = &kl[ni >> 1][(ni & 1) * 2];
                        mma16816(s[ni], qh[ks], bh);
                        mma16816(s[ni], qh[ks], bl);
                        mma16816(s[ni], ql[ks], bh);
                    }
                }
            }

            if (kt * 64 + 63 > qb * 128 + w * 16) {
#pragma unroll
                for (int ni = 0; ni < 8; ni++) {
                    int cb = kt * 64 + ni * 8 + t2;
                    if (cb     > row0) s[ni][0] = -1e9f;
                    if (cb + 1 > row0) s[ni][1] = -1e9f;
                    if (cb     > row1) s[ni][2] = -1e9f;
                    if (cb + 1 > row1) s[ni][3] = -1e9f;
                }
            }

            float mx0 = -INFINITY, mx1 = -INFINITY;
#pragma unroll
            for (int ni = 0; ni < 8; ni++) {
                mx0 = fmaxf(mx0, fmaxf(s[ni][0], s[ni][1]));
                mx1 = fmaxf(mx1, fmaxf(s[ni][2], s[ni][3]));
            }
            mx0 = fmaxf(mx0, __shfl_xor_sync(0xffffffffu, mx0, 1));
            mx0 = fmaxf(mx0, __shfl_xor_sync(0xffffffffu, mx0, 2));
            mx1 = fmaxf(mx1, __shfl_xor_sync(0xffffffffu, mx1, 1));
            mx1 = fmaxf(mx1, __shfl_xor_sync(0xffffffffu, mx1, 2));
            float nm0 = fmaxf(m0, mx0), nm1 = fmaxf(m1, mx1);
            float sc0 = __expf(m0 - nm0), sc1 = __expf(m1 - nm1);
            m0 = nm0; m1 = nm1;
            l0 *= sc0; l1 *= sc1;
#pragma unroll
            for (int nd = 0; nd < 8; nd++) {
                o[nd][0] *= sc0; o[nd][1] *= sc0;
                o[nd][2] *= sc1; o[nd][3] *= sc1;
            }
#pragma unroll
            for (int ni = 0; ni < 8; ni++) {
                s[ni][0] = __expf(s[ni][0] - m0);
                s[ni][1] = __expf(s[ni][1] - m0);
                s[ni][2] = __expf(s[ni][2] - m1);
                s[ni][3] = __expf(s[ni][3] - m1);
                l0 += s[ni][0] + s[ni][1];
                l1 += s[ni][2] + s[ni][3];
            }

            {
                int vrow = ((lane >> 4) & 1) * 8 + (lane & 7);
                int vsel = (lane >> 3) & 1;
#pragma unroll
                for (int kc = 0; kc < 4; kc++) {
                    float p00 = s[2*kc][0],   p01 = s[2*kc][1];
                    float p02 = s[2*kc][2],   p03 = s[2*kc][3];
                    float p10 = s[2*kc+1][0], p11 = s[2*kc+1][1];
                    float p12 = s[2*kc+1][2], p13 = s[2*kc+1][3];
                    uint32_t aph[4], apl[4];
                    {
                        __nv_bfloat162 h0 = __floats2bfloat162_rn(p00, p01);
                        __nv_bfloat162 h1 = __floats2bfloat162_rn(p02, p03);
                        __nv_bfloat162 h2 = __floats2bfloat162_rn(p10, p11);
                        __nv_bfloat162 h3 = __floats2bfloat162_rn(p12, p13);
                        aph[0] = *(uint32_t*)&h0; aph[1] = *(uint32_t*)&h1;
                        aph[2] = *(uint32_t*)&h2; aph[3] = *(uint32_t*)&h3;
                        apl[0] = pack_bf2(p00 - __bfloat162float(h0.x), p01 - __bfloat162float(h0.y));
                        apl[1] = pack_bf2(p02 - __bfloat162float(h1.x), p03 - __bfloat162float(h1.y));
                        apl[2] = pack_bf2(p10 - __bfloat162float(h2.x), p11 - __bfloat162float(h2.y));
                        apl[3] = pack_bf2(p12 - __bfloat162float(h3.x), p13 - __bfloat162float(h3.y));
                    }
                    uint32_t vh[4][4], vl[4][4];
                    int c = 2 * kc + vsel;
#pragma unroll
                    for (int p = 0; p < 4; p++) {
                        uint32_t off = swz8(p * 16 + vrow, c);
                        ldm4(vh[p], skv + 16384 + off);
                        ldm4(vl[p], skv + 24576 + off);
                    }
#pragma unroll
                    for (int nd = 0; nd < 8; nd++) {
                        const uint32_t* bh = &vh[nd >> 1][(nd & 1) * 2];
                        const uint32_t* bl = &vl[nd >> 1][(nd & 1) * 2];
                        mma16816(o[nd], aph, bh);
                        mma16816(o[nd], aph, bl);
                        mma16816(o[nd], apl, bh);
                    }
                }
            }
        }
        __syncthreads();
    }

    l0 += __shfl_xor_sync(0xffffffffu, l0, 1);
    l0 += __shfl_xor_sync(0xffffffffu, l0, 2);
    l1 += __shfl_xor_sync(0xffffffffu, l1, 1);
    l1 += __shfl_xor_sync(0xffffffffu, l1, 2);
    float i0 = 1.f / l0, i1 = 1.f / l1;
#pragma unroll
    for (int nd = 0; nd < 8; nd++) {
        int col = h * DV + nd * 8 + t2;
        float v0 = o[nd][0] * i0, v1 = o[nd][1] * i0;
        float v2 = o[nd][2] * i1, v3 = o[nd][3] * i1;
        __nv_bfloat162 h0 = __floats2bfloat162_rn(v0, v1);
        __nv_bfloat162 h1 = __floats2bfloat162_rn(v2, v3);
        *(uint32_t*)&g_cxh[(size_t)row0 * CTX_COLS + col] = *(uint32_t*)&h0;
        *(uint32_t*)&g_cxh[(size_t)row1 * CTX_COLS + col] = *(uint32_t*)&h1;
        *(uint32_t*)&g_cxl[(size_t)row0 * CTX_COLS + col] =
            pack_bf2(v0 - __bfloat162float(h0.x), v1 - __bfloat162float(h0.y));
        *(uint32_t*)&g_cxl[(size_t)row1 * CTX_COLS + col] =
            pack_bf2(v2 - __bfloat162float(h1.x), v3 - __bfloat162float(h1.y));
    }
}

// ---------------------------------------------------------------------------
// launch
// ---------------------------------------------------------------------------
template <typename T>
static T* sym_addr(const void* sym)
{
    void* p = nullptr;
    cudaGetSymbolAddress(&p, sym);
    return (T*)p;
}

extern "C" void kernel_launch(void* const* d_in, const int* in_sizes, int n_in,
                              void* d_out, int out_size)
{
    const float* x        = (const float*)d_in[0];
    const float* wq_down  = (const float*)d_in[1];
    const float* q_ln_w   = (const float*)d_in[2];
    const float* q_ln_b   = (const float*)d_in[3];
    const float* wq_up    = (const float*)d_in[4];
    const float* wkv_down = (const float*)d_in[5];
    const float* kv_ln_w  = (const float*)d_in[6];
    const float* kv_ln_b  = (const float*)d_in[7];
    const float* wkv_up   = (const float*)d_in[8];
    const float* wo       = (const float*)d_in[9];
    float* out = (float*)d_out;

    // One-time setup (runs on the correctness call, before graph capture).
    static cudaStream_t s1 = nullptr;
    static cudaEvent_t evX = nullptr, evKV = nullptr, evWO = nullptr;
    if (!s1) {
        cudaFuncSetAttribute(mma_gemm2, cudaFuncAttributeMaxDynamicSharedMemorySize, 49152);
        cudaFuncSetAttribute(attn_mma_kernel, cudaFuncAttributeMaxDynamicSharedMemorySize, 65536);
        cudaStreamCreateWithFlags(&s1, cudaStreamNonBlocking);
        cudaEventCreateWithFlags(&evX, cudaEventDisableTiming);
        cudaEventCreateWithFlags(&evKV, cudaEventDisableTiming);
        cudaEventCreateWithFlags(&evWO, cudaEventDisableTiming);
    }

    float* qc  = sym_addr<float>(g_qc);
    float* q   = sym_addr<float>(g_q);
    float* kv  = sym_addr<float>(g_kv);
    float* kvu = sym_addr<float>(g_kvu);

    __nv_bfloat16 *xh  = sym_addr<__nv_bfloat16>(g_xh),  *xl  = sym_addr<__nv_bfloat16>(g_xl);
    __nv_bfloat16 *qch = sym_addr<__nv_bfloat16>(g_qch), *qcl = sym_addr<__nv_bfloat16>(g_qcl);
    __nv_bfloat16 *kch = sym_addr<__nv_bfloat16>(g_kch), *kcl = sym_addr<__nv_bfloat16>(g_kcl);
    __nv_bfloat16 *cxh = sym_addr<__nv_bfloat16>(g_cxh), *cxl = sym_addr<__nv_bfloat16>(g_cxl);
    __nv_bfloat16 *wqdh= sym_addr<__nv_bfloat16>(g_wqdh),*wqdl= sym_addr<__nv_bfloat16>(g_wqdl);
    __nv_bfloat16 *wquh= sym_addr<__nv_bfloat16>(g_wquh),*wqul= sym_addr<__nv_bfloat16>(g_wqul);
    __nv_bfloat16 *wkdh= sym_addr<__nv_bfloat16>(g_wkdh),*wkdl= sym_addr<__nv_bfloat16>(g_wkdl);
    __nv_bfloat16 *wkuh= sym_addr<__nv_bfloat16>(g_wkuh),*wkul= sym_addr<__nv_bfloat16>(g_wkul);
    __nv_bfloat16 *woh = sym_addr<__nv_bfloat16>(g_woh), *wol = sym_addr<__nv_bfloat16>(g_wol);

    dim3 tblk(32, 8);

    // ---- launch #1..#3 on default stream (profiled launch offset: #4) ----
    rope_table_kernel<<<(S_LEN * 16 + 255) / 256, 256>>>();                               // 1
    wsplit_t<<<dim3(QLR_PAD / 32, H_DIM / 32), tblk>>>(wq_down, wqdh, wqdl, H_DIM, QLR);  // 2
    split_kernel<<<(S_LEN * H_DIM / 4 + 255) / 256, 256>>>(x, xh, xl, S_LEN * H_DIM / 4); // 3
    cudaEventRecord(evX, 0);

    // ---- launch #4 — PROFILED: x @ wq_down (K=2048) ----
    mma_gemm2<<<dim3(QLR_PAD / 64, S_LEN / 128), 256, 49152>>>(
        xh, xl, wqdh, wqdl, qc, S_LEN, QLR, H_DIM);

    // ---- kv path on s1 (concurrent with q path) ----
    cudaStreamWaitEvent(s1, evX, 0);
    wsplit_t<<<dim3(KV_PAD / 32, H_DIM / 32), tblk, 0, s1>>>(wkv_down, wkdh, wkdl, H_DIM, KV_COLS);
    mma_gemm2<<<dim3(KV_PAD / 64, S_LEN / 128), 256, 49152, s1>>>(
        xh, xl, wkdh, wkdl, kv, S_LEN, KV_COLS, H_DIM);
    rmsnorm_split<<<S_LEN, 128, 0, s1>>>(kv, kch, kcl, kv_ln_w, kv_ln_b, KVLR, KV_COLS);
    wsplit_t<<<dim3(KVU_COLS / 32, KVLR / 32), tblk, 0, s1>>>(wkv_up, wkuh, wkul, KVLR, KVU_COLS);
    mma_gemm2<<<dim3(KVU_COLS / 64, S_LEN / 128), 256, 49152, s1>>>(
        kch, kcl, wkuh, wkul, kvu, S_LEN, KVU_COLS, KVLR);
    rope_k_kernel<<<(S_LEN + 127) / 128, 128, 0, s1>>>();
    ksplit_kernel<<<(NH * S_LEN * HD + 255) / 256, 256, 0, s1>>>();
    vtsplit_kernel<<<dim3(S_LEN / 32, DV / 32, NH), tblk, 0, s1>>>();
    cudaEventRecord(evKV, s1);
    wsplit_t<<<dim3(H_DIM / 32, CTX_COLS / 32), tblk, 0, s1>>>(wo, woh, wol, CTX_COLS, H_DIM);
    cudaEventRecord(evWO, s1);

    // ---- q path continues on default stream ----
    rmsnorm_split<<<S_LEN, 256>>>(qc, qch, qcl, q_ln_w, q_ln_b, QLR, QLR);
    wsplit_t<<<dim3(Q_COLS / 32, QLR / 32), tblk>>>(wq_up, wquh, wqul, QLR, Q_COLS);
    mma_gemm2<<<dim3(Q_COLS / 64, S_LEN / 128), 256, 49152>>>(
        qch, qcl, wquh, wqul, q, S_LEN, Q_COLS, QLR);
    rope_q_split_kernel<<<(S_LEN * NH + 127) / 128, 128>>>();

    // ---- join: attention needs kv pre-pass + q pre-pass ----
    cudaStreamWaitEvent(0, evKV, 0);
    attn_mma_kernel<<<dim3(16, NH), 256, 65536>>>();

    // ---- output projection (needs wo split) ----
    cudaStreamWaitEvent(0, evWO, 0);
    mma_gemm2<<<dim3(H_DIM / 64, S_LEN / 128), 256, 49152>>>(
        cxh, cxl, woh, wol, out, S_LEN, H_DIM, CTX_COLS);
}

// round 15
// speedup vs baseline: 1.1167x; 1.1167x over previous
#include <cuda_runtime.h>
#include <cuda_bf16.h>
#include <math.h>
#include <stdint.h>

// ---------------------------------------------------------------------------
// Problem constants
// ---------------------------------------------------------------------------
#define S_LEN 2048
#define H_DIM 2048
#define NH 32
#define QLR 1344
#define QLR_PAD 1408
#define KVLR 128
#define DN 32
#define DR 32
#define DV 64
#define HD 64
#define KV_COLS 160
#define KV_PAD 256
#define KVU_COLS 3072
#define Q_COLS 2048
#define CTX_COLS 2048

// ---------------------------------------------------------------------------
// Scratch (device globals — no allocation allowed)
// ---------------------------------------------------------------------------
__device__ float g_qc [S_LEN * QLR];
__device__ float g_q  [S_LEN * Q_COLS];
__device__ float g_kv [S_LEN * KV_COLS];
__device__ float g_kvu[S_LEN * KVU_COLS];
__device__ float g_cos[S_LEN * 16];
__device__ float g_sin[S_LEN * 16];

// split activations (bf16 hi/lo)
__device__ __nv_bfloat16 g_xh [S_LEN * H_DIM],  g_xl [S_LEN * H_DIM];
__device__ __nv_bfloat16 g_qch[S_LEN * QLR],    g_qcl[S_LEN * QLR];
__device__ __nv_bfloat16 g_kch[S_LEN * KVLR],   g_kcl[S_LEN * KVLR];
__device__ __nv_bfloat16 g_cxh[S_LEN * CTX_COLS], g_cxl[S_LEN * CTX_COLS];
// split + transposed weights: [Npad, K]
__device__ __nv_bfloat16 g_wqdh[QLR_PAD * H_DIM], g_wqdl[QLR_PAD * H_DIM];
__device__ __nv_bfloat16 g_wquh[Q_COLS * QLR],    g_wqul[Q_COLS * QLR];
__device__ __nv_bfloat16 g_wkdh[KV_PAD * H_DIM],  g_wkdl[KV_PAD * H_DIM];
__device__ __nv_bfloat16 g_wkuh[KVU_COLS * KVLR], g_wkul[KVU_COLS * KVLR];
__device__ __nv_bfloat16 g_woh [H_DIM * CTX_COLS], g_wol[H_DIM * CTX_COLS];
// attention operands (bf16 hi/lo, pre-split)
__device__ __nv_bfloat16 g_qsh[S_LEN * Q_COLS],  g_qsl[S_LEN * Q_COLS];   // scaled+roped Q
__device__ __nv_bfloat16 g_akh[NH * S_LEN * HD], g_akl[NH * S_LEN * HD];  // K per head [h][t][64]
__device__ __nv_bfloat16 g_avh[NH * DV * S_LEN], g_avl[NH * DV * S_LEN];  // V^T per head [h][d][t]

// ---------------------------------------------------------------------------
// PTX helpers
// ---------------------------------------------------------------------------
__device__ __forceinline__ uint32_t smem_u32(const void* p) {
    uint32_t a;
    asm("{ .reg .u64 t; cvta.to.shared.u64 t, %1; cvt.u32.u64 %0, t; }" : "=r"(a) : "l"(p));
    return a;
}
__device__ __forceinline__ void mma16816(float* d, const uint32_t* a, const uint32_t* b)
{
    asm volatile(
        "mma.sync.aligned.m16n8k16.row.col.f32.bf16.bf16.f32 "
        "{%0,%1,%2,%3}, {%4,%5,%6,%7}, {%8,%9}, {%0,%1,%2,%3};"
        : "+f"(d[0]), "+f"(d[1]), "+f"(d[2]), "+f"(d[3])
        : "r"(a[0]), "r"(a[1]), "r"(a[2]), "r"(a[3]),
          "r"(b[0]), "r"(b[1]));
}
__device__ __forceinline__ void ldm4(uint32_t* r, uint32_t addr)
{
    asm volatile("ldmatrix.sync.aligned.m8n8.x4.shared.b16 {%0,%1,%2,%3}, [%4];"
        : "=r"(r[0]), "=r"(r[1]), "=r"(r[2]), "=r"(r[3]) : "r"(addr));
}
__device__ __forceinline__ void cp16cg(uint32_t saddr, const void* gaddr)
{
    asm volatile("cp.async.cg.shared.global [%0], [%1], 16;" :: "r"(saddr), "l"(gaddr));
}
__device__ __forceinline__ void cp_commit() { asm volatile("cp.async.commit_group;"); }
template <int N> __device__ __forceinline__ void cp_wait()
{
    asm volatile("cp.async.wait_group %0;" :: "n"(N));
}
// 128B-row swizzle (8 x 16B chunks per row) — GEMM + attention tiles
__device__ __forceinline__ uint32_t swz8(int row, int c)
{
    return (uint32_t)(row * 128 + ((c ^ (row & 7)) << 4));
}
__device__ __forceinline__ uint32_t pack_bf2(float a, float b)
{
    __nv_bfloat162 t = __floats2bfloat162_rn(a, b);
    return *(uint32_t*)&t;
}

// ---------------------------------------------------------------------------
// GEMM v6: C[M,N] fp32 = A[M,K] @ B^T, bf16 hi/lo. CTA 128x64x64, 8 warps
// (4M x 2N), warp tile 32x32. K-chunk 64 halves barrier count vs K32;
// 2 stages x 48KB = 96KB smem + launch_bounds(256,2) -> 2 CTAs/SM (192KB).
// 128B-row swz8 layout = same geometry as the validated attention tiles.
// ---------------------------------------------------------------------------
#define ST_AH 0
#define ST_AL 16384
#define ST_BH 32768
#define ST_BL 40960
#define ST_SZ 49152
#define G_SMEM (2 * ST_SZ)

__global__ __launch_bounds__(256, 2) void mma_gemm2(
    const __nv_bfloat16* __restrict__ Ah, const __nv_bfloat16* __restrict__ Al,
    const __nv_bfloat16* __restrict__ Bh, const __nv_bfloat16* __restrict__ Bl,
    float* __restrict__ C, int M, int N, int K)
{
    extern __shared__ uint8_t dsm[];
    const uint32_t sbase = smem_u32(dsm);
    const int tid = threadIdx.x, lane = tid & 31, wid = tid >> 5;
    const int wm = wid & 3, wn = wid >> 2;
    const int m0 = blockIdx.y * 128, n0 = blockIdx.x * 64;
    const int g = lane >> 2, t2 = (lane & 3) * 2;

    float acc[2][4][4];
#pragma unroll
    for (int mi = 0; mi < 2; mi++)
#pragma unroll
        for (int ni = 0; ni < 4; ni++)
#pragma unroll
            for (int j = 0; j < 4; j++) acc[mi][ni][j] = 0.f;

    auto load_stage = [&](int s, int k0) {
        uint32_t sb = sbase + s * ST_SZ;
        // A tiles: 128 rows x 64 cols bf16 (hi,lo) = 1024 16B units each
#pragma unroll
        for (int i = 0; i < 8; i++) {
            int u = tid + 256 * i;
            int v = u & 1023;
            int row = v >> 3, c = v & 7;
            uint32_t soff = swz8(row, c);
            const __nv_bfloat16* gp = (i < 4) ? Ah : Al;
            uint32_t so = (i < 4) ? ST_AH : ST_AL;
            cp16cg(sb + so + soff, gp + (size_t)(m0 + row) * K + k0 + c * 8);
        }
        // B tiles: 64 rows x 64 cols bf16 (hi,lo) = 512 16B units each
#pragma unroll
        for (int i = 0; i < 4; i++) {
            int u = tid + 256 * i;
            int v = u & 511;
            int row = v >> 3, c = v & 7;
            uint32_t soff = swz8(row, c);
            const __nv_bfloat16* gp = (i < 2) ? Bh : Bl;
            uint32_t so = (i < 2) ? ST_BH : ST_BL;
            cp16cg(sb + so + soff, gp + (size_t)(n0 + row) * K + k0 + c * 8);
        }
    };

    const int nch = K / 64;
    load_stage(0, 0);
    cp_commit();

    for (int ci = 0; ci < nch; ci++) {
        if (ci + 1 < nch) {
            load_stage((ci + 1) & 1, (ci + 1) * 64);
            cp_commit();
            cp_wait<1>();
        } else {
            cp_wait<0>();
        }
        __syncthreads();

        const uint32_t sa = sbase + (ci & 1) * ST_SZ;
#pragma unroll
        for (int ks = 0; ks < 4; ks++) {
            uint32_t ah[2][4], alr[2][4];
#pragma unroll
            for (int mi = 0; mi < 2; mi++) {
                int row = wm * 32 + mi * 16 + (lane & 15);
                int c = 2 * ks + (lane >> 4);
                uint32_t off = swz8(row, c);
                ldm4(ah[mi],  sa + ST_AH + off);
                ldm4(alr[mi], sa + ST_AL + off);
            }
            uint32_t bh[4][2], bl[4][2];
#pragma unroll
            for (int p = 0; p < 2; p++) {
                int row = wn * 32 + p * 16 + ((lane >> 4) & 1) * 8 + (lane & 7);
                int c = 2 * ks + ((lane >> 3) & 1);
                uint32_t off = swz8(row, c);
                uint32_t th[4], tl[4];
                ldm4(th, sa + ST_BH + off);
                ldm4(tl, sa + ST_BL + off);
                bh[2*p][0] = th[0]; bh[2*p][1] = th[1];
                bh[2*p+1][0] = th[2]; bh[2*p+1][1] = th[3];
                bl[2*p][0] = tl[0]; bl[2*p][1] = tl[1];
                bl[2*p+1][0] = tl[2]; bl[2*p+1][1] = tl[3];
            }
#pragma unroll
            for (int mi = 0; mi < 2; mi++)
#pragma unroll
                for (int ni = 0; ni < 4; ni++) {
                    mma16816(acc[mi][ni], ah[mi],  bh[ni]);
                    mma16816(acc[mi][ni], ah[mi],  bl[ni]);
                    mma16816(acc[mi][ni], alr[mi], bh[ni]);
                }
        }
        __syncthreads();
    }

#pragma unroll
    for (int mi = 0; mi < 2; mi++) {
        int row = m0 + wm * 32 + mi * 16 + g;
#pragma unroll
        for (int ni = 0; ni < 4; ni++) {
            int col = n0 + wn * 32 + ni * 8 + t2;
            if (col < N) {
                float2 v0 = {acc[mi][ni][0], acc[mi][ni][1]};
                float2 v1 = {acc[mi][ni][2], acc[mi][ni][3]};
                *(float2*)&C[(size_t)row * N + col]       = v0;
                *(float2*)&C[(size_t)(row + 8) * N + col] = v1;
            }
        }
    }
}

// ---------------------------------------------------------------------------
// Weight transpose + split
// ---------------------------------------------------------------------------
__global__ void wsplit_t(const float* __restrict__ W,
                         __nv_bfloat16* __restrict__ Th,
                         __nv_bfloat16* __restrict__ Tl,
                         int Kw, int Nw)
{
    __shared__ float t[32][33];
    int n0 = blockIdx.x * 32, k0 = blockIdx.y * 32;
    int tx = threadIdx.x, ty = threadIdx.y;
#pragma unroll
    for (int j = 0; j < 32; j += 8) {
        int k = k0 + ty + j, n = n0 + tx;
        t[ty + j][tx] = (n < Nw) ? W[(size_t)k * Nw + n] : 0.f;
    }
    __syncthreads();
#pragma unroll
    for (int j = 0; j < 32; j += 8) {
        int n = n0 + ty + j, k = k0 + tx;
        float v = t[tx][ty + j];
        __nv_bfloat16 h = __float2bfloat16(v);
        Th[(size_t)n * Kw + k] = h;
        Tl[(size_t)n * Kw + k] = __float2bfloat16(v - __bfloat162float(h));
    }
}

// ---------------------------------------------------------------------------
// fp32 -> bf16 hi/lo split (vectorized)
// ---------------------------------------------------------------------------
__global__ void split_kernel(const float* __restrict__ x,
                             __nv_bfloat16* __restrict__ h,
                             __nv_bfloat16* __restrict__ l, int n4)
{
    int i = blockIdx.x * blockDim.x + threadIdx.x;
    if (i >= n4) return;
    float4 v = ((const float4*)x)[i];
    float vv[4] = {v.x, v.y, v.z, v.w};
    __nv_bfloat16 hh[4], ll[4];
#pragma unroll
    for (int k = 0; k < 4; k++) {
        hh[k] = __float2bfloat16(vv[k]);
        ll[k] = __float2bfloat16(vv[k] - __bfloat162float(hh[k]));
    }
    ((uint2*)h)[i] = *(uint2*)hh;
    ((uint2*)l)[i] = *(uint2*)ll;
}

// ---------------------------------------------------------------------------
// RMSNorm with fused bf16 hi/lo split output
// ---------------------------------------------------------------------------
__global__ void rmsnorm_split(const float* __restrict__ in,
                              __nv_bfloat16* __restrict__ oh,
                              __nv_bfloat16* __restrict__ ol,
                              const float* __restrict__ w, const float* __restrict__ b,
                              int cols, int in_ld)
{
    int row = blockIdx.x;
    const float* x = in + (size_t)row * in_ld;
    float ss = 0.f;
    for (int c = threadIdx.x; c < cols; c += blockDim.x) {
        float v = x[c];
        ss = fmaf(v, v, ss);
    }
    __shared__ float red[8];
#pragma unroll
    for (int o = 16; o > 0; o >>= 1) ss += __shfl_down_sync(0xffffffffu, ss, o);
    if ((threadIdx.x & 31) == 0) red[threadIdx.x >> 5] = ss;
    __syncthreads();
    if (threadIdx.x == 0) {
        float tot = 0.f;
        for (int i = 0; i < (int)(blockDim.x >> 5); i++) tot += red[i];
        red[0] = rsqrtf(tot / (float)cols + 1e-5f);
    }
    __syncthreads();
    float inv = red[0];
    for (int c = threadIdx.x; c < cols; c += blockDim.x) {
        float v = fmaf(w[c], x[c] * inv, b[c]);
        __nv_bfloat16 h = __float2bfloat16(v);
        oh[(size_t)row * cols + c] = h;
        ol[(size_t)row * cols + c] = __float2bfloat16(v - __bfloat162float(h));
    }
}

// ---------------------------------------------------------------------------
// RoPE table
// ---------------------------------------------------------------------------
__global__ void rope_table_kernel()
{
    int idx = blockIdx.x * blockDim.x + threadIdx.x;
    if (idx >= S_LEN * 16) return;
    int t = idx >> 4, i = idx & 15;
    double inv_freq = exp(-((double)(2 * i) / 32.0) * log(500000.0));
    double a = (double)t * inv_freq;
    g_cos[idx] = (float)cos(a);
    g_sin[idx] = (float)sin(a);
}

// ---------------------------------------------------------------------------
// Fused: rope(q) + scale + bf16 split
// ---------------------------------------------------------------------------
__global__ void rope_q_split_kernel()
{
    int idx = blockIdx.x * blockDim.x + threadIdx.x;
    if (idx >= S_LEN * NH) return;
    int s = idx / NH, h = idx % NH;
    const float* p = g_q + (size_t)s * Q_COLS + h * HD;
    float v[64];
#pragma unroll
    for (int d = 0; d < 64; d += 4) {
        float4 t = *(const float4*)&p[d];
        v[d] = t.x; v[d+1] = t.y; v[d+2] = t.z; v[d+3] = t.w;
    }
    float x[32];
#pragma unroll
    for (int i = 0; i < 32; i++) x[i] = v[32 + i];
#pragma unroll
    for (int i = 0; i < 16; i++) {
        float c = g_cos[s * 16 + i], sn = g_sin[s * 16 + i];
        v[32 + i] = fmaf(x[2 * i], c, -x[2 * i + 1] * sn);
        v[48 + i] = fmaf(x[2 * i + 1], c, x[2 * i] * sn);
    }
    size_t base = (size_t)s * Q_COLS + h * HD;
#pragma unroll
    for (int d = 0; d < 64; d += 2) {
        float a = v[d] * 0.125f, b = v[d + 1] * 0.125f;
        __nv_bfloat162 hh = __floats2bfloat162_rn(a, b);
        *(uint32_t*)&g_qsh[base + d] = *(uint32_t*)&hh;
        *(uint32_t*)&g_qsl[base + d] =
            pack_bf2(a - __bfloat162float(hh.x), b - __bfloat162float(hh.y));
    }
}

__global__ void rope_k_kernel()
{
    int s = blockIdx.x * blockDim.x + threadIdx.x;
    if (s >= S_LEN) return;
    float* p = g_kv + (size_t)s * KV_COLS + KVLR;
    float x[32];
#pragma unroll
    for (int i = 0; i < 32; i++) x[i] = p[i];
#pragma unroll
    for (int i = 0; i < 16; i++) {
        float c = g_cos[s * 16 + i], sn = g_sin[s * 16 + i];
        p[i]      = fmaf(x[2 * i], c, -x[2 * i + 1] * sn);
        p[i + 16] = fmaf(x[2 * i + 1], c, x[2 * i] * sn);
    }
}

// ---------------------------------------------------------------------------
// Attention pre-pass: assemble K per head (bf16 hi/lo) [h][t][64]
// ---------------------------------------------------------------------------
__global__ void ksplit_kernel()
{
    int u = blockIdx.x * blockDim.x + threadIdx.x;
    if (u >= NH * S_LEN * HD) return;
    int d = u & 63, t = (u >> 6) & 2047, h = u >> 17;
    float v = (d < DN) ? g_kvu[(size_t)t * KVU_COLS + h * 96 + d]
                       : g_kv [(size_t)t * KV_COLS + KVLR + (d - DN)];
    __nv_bfloat16 hh = __float2bfloat16(v);
    g_akh[u] = hh;
    g_akl[u] = __float2bfloat16(v - __bfloat162float(hh));
}

// ---------------------------------------------------------------------------
// Attention pre-pass: transpose V per head -> [h][d][t], bf16 hi/lo
// ---------------------------------------------------------------------------
__global__ void vtsplit_kernel()
{
    __shared__ float sm[32][33];
    int t0 = blockIdx.x * 32, d0 = blockIdx.y * 32, h = blockIdx.z;
    int tx = threadIdx.x, ty = threadIdx.y;
#pragma unroll
    for (int j = 0; j < 32; j += 8) {
        int t = t0 + ty + j, d = d0 + tx;
        sm[ty + j][tx] = g_kvu[(size_t)t * KVU_COLS + h * 96 + DN + d];
    }
    __syncthreads();
#pragma unroll
    for (int j = 0; j < 32; j += 8) {
        int d = d0 + ty + j, t = t0 + tx;
        float v = sm[tx][ty + j];
        __nv_bfloat16 hh = __float2bfloat16(v);
        size_t idx = ((size_t)h * DV + d) * S_LEN + t;
        g_avh[idx] = hh;
        g_avl[idx] = __float2bfloat16(v - __bfloat162float(hh));
    }
}

// ---------------------------------------------------------------------------
// Tensor-core flash attention (R12 config: 96KB smem, 1 CTA/SM),
// double-buffered K/V staging.
// ---------------------------------------------------------------------------
#define AT_KV0 32768

__global__ __launch_bounds__(256) void attn_mma_kernel()
{
    extern __shared__ uint8_t dsm[];
    const int qb = 15 - blockIdx.x;        // heavy blocks first
    const int h  = blockIdx.y;
    const int tid = threadIdx.x, lane = tid & 31, w = tid >> 5;
    const int g = lane >> 2, t2 = (lane & 3) * 2;
    const uint32_t sb = smem_u32(dsm);

    auto stage_kv = [&](int buf, int kt) {
        uint32_t skv = sb + AT_KV0 + buf * 32768;
#pragma unroll
        for (int i = 0; i < 8; i++) {
            int u = tid + 256 * i;
            int arr = u >> 9;
            int v = u & 511;
            int row = v >> 3, c = v & 7;
            const __nv_bfloat16* src;
            if (arr == 0)
                src = g_akh + ((size_t)h * S_LEN + kt * 64 + row) * HD + c * 8;
            else if (arr == 1)
                src = g_akl + ((size_t)h * S_LEN + kt * 64 + row) * HD + c * 8;
            else if (arr == 2)
                src = g_avh + ((size_t)h * DV + row) * S_LEN + kt * 64 + c * 8;
            else
                src = g_avl + ((size_t)h * DV + row) * S_LEN + kt * 64 + c * 8;
            cp16cg(skv + arr * 8192 + swz8(row, c), src);
        }
    };

    // stage Q (hi/lo) + first KV tile
#pragma unroll
    for (int i = 0; i < 8; i++) {
        int u = tid + 256 * i;
        int half = u >> 10;
        int v = u & 1023;
        int row = v >> 3, c = v & 7;
        const __nv_bfloat16* src = (half ? g_qsl : g_qsh)
            + (size_t)(qb * 128 + row) * Q_COLS + h * HD + c * 8;
        cp16cg(sb + half * 16384 + swz8(row, c), src);
    }
    cp_commit();
    stage_kv(0, 0);
    cp_commit();
    cp_wait<0>();
    __syncthreads();

    uint32_t qh[4][4], ql[4][4];
    {
        int row = w * 16 + (lane & 15);
#pragma unroll
        for (int ks = 0; ks < 4; ks++) {
            int c = 2 * ks + (lane >> 4);
            uint32_t off = swz8(row, c);
            ldm4(qh[ks], sb + off);
            ldm4(ql[ks], sb + 16384 + off);
        }
    }

    float o[8][4];
#pragma unroll
    for (int nd = 0; nd < 8; nd++)
#pragma unroll
        for (int j = 0; j < 4; j++) o[nd][j] = 0.f;
    float m0 = -INFINITY, m1 = -INFINITY, l0 = 0.f, l1 = 0.f;

    const int row0 = qb * 128 + w * 16 + g;
    const int row1 = row0 + 8;
    const int wmax = qb * 128 + w * 16 + 15;
    const int ktmax = 2 * qb + 1;

    for (int kt = 0; kt <= ktmax; kt++) {
        if (kt + 1 <= ktmax) {
            stage_kv((kt + 1) & 1, kt + 1);
            cp_commit();
            cp_wait<1>();
        } else {
            cp_wait<0>();
        }
        __syncthreads();

        const uint32_t skv = sb + AT_KV0 + (kt & 1) * 32768;

        if (kt * 64 <= wmax) {
            float s[8][4];
#pragma unroll
            for (int ni = 0; ni < 8; ni++)
#pragma unroll
                for (int j = 0; j < 4; j++) s[ni][j] = 0.f;

            {
                int krow = ((lane >> 4) & 1) * 8 + (lane & 7);
                int ksel = (lane >> 3) & 1;
#pragma unroll
                for (int ks = 0; ks < 4; ks++) {
                    uint32_t kh[4][4], kl[4][4];
                    int c = 2 * ks + ksel;
#pragma unroll
                    for (int p = 0; p < 4; p++) {
                        uint32_t off = swz8(p * 16 + krow, c);
                        ldm4(kh[p], skv + off);
                        ldm4(kl[p], skv + 8192 + off);
                    }
#pragma unroll
                    for (int ni = 0; ni < 8; ni++) {
                        const uint32_t* bh = &kh[ni >> 1][(ni & 1) * 2];
                        const uint32_t* bl = &kl[ni >> 1][(ni & 1) * 2];
                        mma16816(s[ni], qh[ks], bh);
                        mma16816(s[ni], qh[ks], bl);
                        mma16816(s[ni], ql[ks], bh);
                    }
                }
            }

            if (kt * 64 + 63 > qb * 128 + w * 16) {
#pragma unroll
                for (int ni = 0; ni < 8; ni++) {
                    int cb = kt * 64 + ni * 8 + t2;
                    if (cb     > row0) s[ni][0] = -1e9f;
                    if (cb + 1 > row0) s[ni][1] = -1e9f;
                    if (cb     > row1) s[ni][2] = -1e9f;
                    if (cb + 1 > row1) s[ni][3] = -1e9f;
                }
            }

            float mx0 = -INFINITY, mx1 = -INFINITY;
#pragma unroll
            for (int ni = 0; ni < 8; ni++) {
                mx0 = fmaxf(mx0, fmaxf(s[ni][0], s[ni][1]));
                mx1 = fmaxf(mx1, fmaxf(s[ni][2], s[ni][3]));
            }
            mx0 = fmaxf(mx0, __shfl_xor_sync(0xffffffffu, mx0, 1));
            mx0 = fmaxf(mx0, __shfl_xor_sync(0xffffffffu, mx0, 2));
            mx1 = fmaxf(mx1, __shfl_xor_sync(0xffffffffu, mx1, 1));
            mx1 = fmaxf(mx1, __shfl_xor_sync(0xffffffffu, mx1, 2));
            float nm0 = fmaxf(m0, mx0), nm1 = fmaxf(m1, mx1);
            float sc0 = __expf(m0 - nm0), sc1 = __expf(m1 - nm1);
            m0 = nm0; m1 = nm1;
            l0 *= sc0; l1 *= sc1;
#pragma unroll
            for (int nd = 0; nd < 8; nd++) {
                o[nd][0] *= sc0; o[nd][1] *= sc0;
                o[nd][2] *= sc1; o[nd][3] *= sc1;
            }
#pragma unroll
            for (int ni = 0; ni < 8; ni++) {
                s[ni][0] = __expf(s[ni][0] - m0);
                s[ni][1] = __expf(s[ni][1] - m0);
                s[ni][2] = __expf(s[ni][2] - m1);
                s[ni][3] = __expf(s[ni][3] - m1);
                l0 += s[ni][0] + s[ni][1];
                l1 += s[ni][2] + s[ni][3];
            }

            {
                int vrow = ((lane >> 4) & 1) * 8 + (lane & 7);
                int vsel = (lane >> 3) & 1;
#pragma unroll
                for (int kc = 0; kc < 4; kc++) {
                    float p00 = s[2*kc][0],   p01 = s[2*kc][1];
                    float p02 = s[2*kc][2],   p03 = s[2*kc][3];
                    float p10 = s[2*kc+1][0], p11 = s[2*kc+1][1];
                    float p12 = s[2*kc+1][2], p13 = s[2*kc+1][3];
                    uint32_t aph[4], apl[4];
                    {
                        __nv_bfloat162 h0 = __floats2bfloat162_rn(p00, p01);
                        __nv_bfloat162 h1 = __floats2bfloat162_rn(p02, p03);
                        __nv_bfloat162 h2 = __floats2bfloat162_rn(p10, p11);
                        __nv_bfloat162 h3 = __floats2bfloat162_rn(p12, p13);
                        aph[0] = *(uint32_t*)&h0; aph[1] = *(uint32_t*)&h1;
                        aph[2] = *(uint32_t*)&h2; aph[3] = *(uint32_t*)&h3;
                        apl[0] = pack_bf2(p00 - __bfloat162float(h0.x), p01 - __bfloat162float(h0.y));
                        apl[1] = pack_bf2(p02 - __bfloat162float(h1.x), p03 - __bfloat162float(h1.y));
                        apl[2] = pack_bf2(p10 - __bfloat162float(h2.x), p11 - __bfloat162float(h2.y));
                        apl[3] = pack_bf2(p12 - __bfloat162float(h3.x), p13 - __bfloat162float(h3.y));
                    }
                    uint32_t vh[4][4], vl[4][4];
                    int c = 2 * kc + vsel;
#pragma unroll
                    for (int p = 0; p < 4; p++) {
                        uint32_t off = swz8(p * 16 + vrow, c);
                        ldm4(vh[p], skv + 16384 + off);
                        ldm4(vl[p], skv + 24576 + off);
                    }
#pragma unroll
                    for (int nd = 0; nd < 8; nd++) {
                        const uint32_t* bh = &vh[nd >> 1][(nd & 1) * 2];
                        const uint32_t* bl = &vl[nd >> 1][(nd & 1) * 2];
                        mma16816(o[nd], aph, bh);
                        mma16816(o[nd], aph, bl);
                        mma16816(o[nd], apl, bh);
                    }
                }
            }
        }
        __syncthreads();
    }

    l0 += __shfl_xor_sync(0xffffffffu, l0, 1);
    l0 += __shfl_xor_sync(0xffffffffu, l0, 2);
    l1 += __shfl_xor_sync(0xffffffffu, l1, 1);
    l1 += __shfl_xor_sync(0xffffffffu, l1, 2);
    float i0 = 1.f / l0, i1 = 1.f / l1;
#pragma unroll
    for (int nd = 0; nd < 8; nd++) {
        int col = h * DV + nd * 8 + t2;
        float v0 = o[nd][0] * i0, v1 = o[nd][1] * i0;
        float v2 = o[nd][2] * i1, v3 = o[nd][3] * i1;
        __nv_bfloat162 h0 = __floats2bfloat162_rn(v0, v1);
        __nv_bfloat162 h1 = __floats2bfloat162_rn(v2, v3);
        *(uint32_t*)&g_cxh[(size_t)row0 * CTX_COLS + col] = *(uint32_t*)&h0;
        *(uint32_t*)&g_cxh[(size_t)row1 * CTX_COLS + col] = *(uint32_t*)&h1;
        *(uint32_t*)&g_cxl[(size_t)row0 * CTX_COLS + col] =
            pack_bf2(v0 - __bfloat162float(h0.x), v1 - __bfloat162float(h0.y));
        *(uint32_t*)&g_cxl[(size_t)row1 * CTX_COLS + col] =
            pack_bf2(v2 - __bfloat162float(h1.x), v3 - __bfloat162float(h1.y));
    }
}

// ---------------------------------------------------------------------------
// launch
// ---------------------------------------------------------------------------
template <typename T>
static T* sym_addr(const void* sym)
{
    void* p = nullptr;
    cudaGetSymbolAddress(&p, sym);
    return (T*)p;
}

extern "C" void kernel_launch(void* const* d_in, const int* in_sizes, int n_in,
                              void* d_out, int out_size)
{
    const float* x        = (const float*)d_in[0];
    const float* wq_down  = (const float*)d_in[1];
    const float* q_ln_w   = (const float*)d_in[2];
    const float* q_ln_b   = (const float*)d_in[3];
    const float* wq_up    = (const float*)d_in[4];
    const float* wkv_down = (const float*)d_in[5];
    const float* kv_ln_w  = (const float*)d_in[6];
    const float* kv_ln_b  = (const float*)d_in[7];
    const float* wkv_up   = (const float*)d_in[8];
    const float* wo       = (const float*)d_in[9];
    float* out = (float*)d_out;

    // One-time setup (runs on the correctness call, before graph capture).
    static cudaStream_t s1 = nullptr;
    static cudaEvent_t evX = nullptr, evKV = nullptr, evWO = nullptr;
    if (!s1) {
        cudaFuncSetAttribute(mma_gemm2, cudaFuncAttributeMaxDynamicSharedMemorySize, G_SMEM);
        cudaFuncSetAttribute(attn_mma_kernel, cudaFuncAttributeMaxDynamicSharedMemorySize, 98304);
        cudaStreamCreateWithFlags(&s1, cudaStreamNonBlocking);
        cudaEventCreateWithFlags(&evX, cudaEventDisableTiming);
        cudaEventCreateWithFlags(&evKV, cudaEventDisableTiming);
        cudaEventCreateWithFlags(&evWO, cudaEventDisableTiming);
    }

    float* qc  = sym_addr<float>(g_qc);
    float* q   = sym_addr<float>(g_q);
    float* kv  = sym_addr<float>(g_kv);
    float* kvu = sym_addr<float>(g_kvu);

    __nv_bfloat16 *xh  = sym_addr<__nv_bfloat16>(g_xh),  *xl  = sym_addr<__nv_bfloat16>(g_xl);
    __nv_bfloat16 *qch = sym_addr<__nv_bfloat16>(g_qch), *qcl = sym_addr<__nv_bfloat16>(g_qcl);
    __nv_bfloat16 *kch = sym_addr<__nv_bfloat16>(g_kch), *kcl = sym_addr<__nv_bfloat16>(g_kcl);
    __nv_bfloat16 *cxh = sym_addr<__nv_bfloat16>(g_cxh), *cxl = sym_addr<__nv_bfloat16>(g_cxl);
    __nv_bfloat16 *wqdh= sym_addr<__nv_bfloat16>(g_wqdh),*wqdl= sym_addr<__nv_bfloat16>(g_wqdl);
    __nv_bfloat16 *wquh= sym_addr<__nv_bfloat16>(g_wquh),*wqul= sym_addr<__nv_bfloat16>(g_wqul);
    __nv_bfloat16 *wkdh= sym_addr<__nv_bfloat16>(g_wkdh),*wkdl= sym_addr<__nv_bfloat16>(g_wkdl);
    __nv_bfloat16 *wkuh= sym_addr<__nv_bfloat16>(g_wkuh),*wkul= sym_addr<__nv_bfloat16>(g_wkul);
    __nv_bfloat16 *woh = sym_addr<__nv_bfloat16>(g_woh), *wol = sym_addr<__nv_bfloat16>(g_wol);

    dim3 tblk(32, 8);

    // ---- launch #1..#3 on default stream (profiled launch offset: #4) ----
    rope_table_kernel<<<(S_LEN * 16 + 255) / 256, 256>>>();                               // 1
    wsplit_t<<<dim3(QLR_PAD / 32, H_DIM / 32), tblk>>>(wq_down, wqdh, wqdl, H_DIM, QLR);  // 2
    split_kernel<<<(S_LEN * H_DIM / 4 + 255) / 256, 256>>>(x, xh, xl, S_LEN * H_DIM / 4); // 3
    cudaEventRecord(evX, 0);

    // ---- launch #4 — PROFILED: x @ wq_down (K=2048) ----
    mma_gemm2<<<dim3(QLR_PAD / 64, S_LEN / 128), 256, G_SMEM>>>(
        xh, xl, wqdh, wqdl, qc, S_LEN, QLR, H_DIM);

    // ---- kv path on s1 (concurrent with q path) ----
    cudaStreamWaitEvent(s1, evX, 0);
    wsplit_t<<<dim3(KV_PAD / 32, H_DIM / 32), tblk, 0, s1>>>(wkv_down, wkdh, wkdl, H_DIM, KV_COLS);
    mma_gemm2<<<dim3(KV_PAD / 64, S_LEN / 128), 256, G_SMEM, s1>>>(
        xh, xl, wkdh, wkdl, kv, S_LEN, KV_COLS, H_DIM);
    rmsnorm_split<<<S_LEN, 128, 0, s1>>>(kv, kch, kcl, kv_ln_w, kv_ln_b, KVLR, KV_COLS);
    wsplit_t<<<dim3(KVU_COLS / 32, KVLR / 32), tblk, 0, s1>>>(wkv_up, wkuh, wkul, KVLR, KVU_COLS);
    mma_gemm2<<<dim3(KVU_COLS / 64, S_LEN / 128), 256, G_SMEM, s1>>>(
        kch, kcl, wkuh, wkul, kvu, S_LEN, KVU_COLS, KVLR);
    rope_k_kernel<<<(S_LEN + 127) / 128, 128, 0, s1>>>();
    ksplit_kernel<<<(NH * S_LEN * HD + 255) / 256, 256, 0, s1>>>();
    vtsplit_kernel<<<dim3(S_LEN / 32, DV / 32, NH), tblk, 0, s1>>>();
    cudaEventRecord(evKV, s1);
    wsplit_t<<<dim3(H_DIM / 32, CTX_COLS / 32), tblk, 0, s1>>>(wo, woh, wol, CTX_COLS, H_DIM);
    cudaEventRecord(evWO, s1);

    // ---- q path continues on default stream ----
    rmsnorm_split<<<S_LEN, 256>>>(qc, qch, qcl, q_ln_w, q_ln_b, QLR, QLR);
    wsplit_t<<<dim3(Q_COLS / 32, QLR / 32), tblk>>>(wq_up, wquh, wqul, QLR, Q_COLS);
    mma_gemm2<<<dim3(Q_COLS / 64, S_LEN / 128), 256, G_SMEM>>>(
        qch, qcl, wquh, wqul, q, S_LEN, Q_COLS, QLR);
    rope_q_split_kernel<<<(S_LEN * NH + 127) / 128, 128>>>();

    // ---- join: attention needs kv pre-pass + q pre-pass ----
    cudaStreamWaitEvent(0, evKV, 0);
    attn_mma_kernel<<<dim3(16, NH), 256, 98304>>>();

    // ---- output projection (needs wo split) ----
    cudaStreamWaitEvent(0, evWO, 0);
    mma_gemm2<<<dim3(H_DIM / 64, S_LEN / 128), 256, G_SMEM>>>(
        cxh, cxl, woh, wol, out, S_LEN, H_DIM, CTX_COLS);
}